// round 16
// baseline (speedup 1.0000x reference)
#include <cuda_runtime.h>
#include <cuda_bf16.h>
#include <math.h>

// Problem shape (fixed by the dataset):
//   B=64, T=512, D_in=256, D_out=1024, M=8 (module_size=128)
// Phase 1: u = x@W_in + b_in into the ys region of d_out (f32x2 GEMM).
// Phase 2: h@W_h never mixes batch rows -> 2 FULLY INDEPENDENT groups of
//   64 CTAs (group g owns rows [32g,+32)). CTA = 32 rows x 16 cols; warp =
//   64-k slice with R14's proven microtile ratio: per k = 1 LDG.128 (4 h
//   rows, 128B/warp coalesced) + one 16B LDS per 8-lane group (4 distinct
//   lines/warp, conflict-free) + 8 FFMA2. Per-group two-hop flag barrier
//   (leader polls 64 flags); ys/h_final stores moved AFTER the release-wait
//   so only the hdst store + fence + flag sit on the inter-step chain.

#define B_      64
#define T_      512
#define DIN     256
#define DOUT    1024
#define BSTR    ((size_t)T_ * DOUT)
#define YS_ELEMS ((size_t)B_ * T_ * DOUT)

typedef unsigned long long ull;

// ---------------------------------------------------------------------------
// Packed-fp32 helpers (Blackwell f32x2)
// ---------------------------------------------------------------------------
__device__ __forceinline__ ull dupf(float x) {
    ull r;
    asm("mov.b64 %0, {%1, %1};" : "=l"(r) : "f"(x));
    return r;
}
__device__ __forceinline__ void ffma2(ull& d, ull a, ull b) {
    asm("fma.rn.f32x2 %0, %1, %2, %0;" : "+l"(d) : "l"(a), "l"(b));
}
__device__ __forceinline__ ull addf2(ull a, ull b) {
    ull r;
    asm("add.rn.f32x2 %0, %1, %2;" : "=l"(r) : "l"(a), "l"(b));
    return r;
}

// ---------------------------------------------------------------------------
// Phase 1: u = X @ W_in + b_in     (M=32768, N=1024, K=256)  [unchanged]
// ---------------------------------------------------------------------------
__global__ void __launch_bounds__(256) phase1_gemm(
    const float* __restrict__ X, const float* __restrict__ Win,
    const float* __restrict__ bin, float* __restrict__ out)
{
    __shared__ float As[16 * 132];
    __shared__ float Bs[16 * 68];

    const int tid = threadIdx.x;
    const int tn0 = blockIdx.x * 64;
    const int tm0 = blockIdx.y * 128;
    const int ty  = tid >> 4;
    const int tx  = tid & 15;

    ull acc01[8], acc23[8];
#pragma unroll
    for (int i = 0; i < 8; i++) { acc01[i] = 0ull; acc23[i] = 0ull; }

    const int arow  = tid >> 1;
    const int akoff = (tid & 1) * 8;
    const int bk    = tid >> 4;
    const int bn    = (tid & 15) * 4;

    for (int kc = 0; kc < DIN; kc += 16) {
        const float* ap = &X[(size_t)(tm0 + arow) * DIN + kc + akoff];
        float4 a0 = *(const float4*)(ap);
        float4 a1 = *(const float4*)(ap + 4);
        float4 b0 = *(const float4*)&Win[(size_t)(kc + bk) * DOUT + tn0 + bn];

        __syncthreads();
        As[(akoff + 0) * 132 + arow] = a0.x;
        As[(akoff + 1) * 132 + arow] = a0.y;
        As[(akoff + 2) * 132 + arow] = a0.z;
        As[(akoff + 3) * 132 + arow] = a0.w;
        As[(akoff + 4) * 132 + arow] = a1.x;
        As[(akoff + 5) * 132 + arow] = a1.y;
        As[(akoff + 6) * 132 + arow] = a1.z;
        As[(akoff + 7) * 132 + arow] = a1.w;
        *(float4*)&Bs[bk * 68 + bn] = b0;
        __syncthreads();

#pragma unroll
        for (int kk = 0; kk < 16; kk++) {
            float4 af0 = *(const float4*)&As[kk * 132 + ty * 8];
            float4 af1 = *(const float4*)&As[kk * 132 + ty * 8 + 4];
            ulonglong2 bb = *(const ulonglong2*)&Bs[kk * 68 + tx * 4];
            float a[8] = {af0.x, af0.y, af0.z, af0.w, af1.x, af1.y, af1.z, af1.w};
#pragma unroll
            for (int i = 0; i < 8; i++) {
                ull ad = dupf(a[i]);
                ffma2(acc01[i], ad, bb.x);
                ffma2(acc23[i], ad, bb.y);
            }
        }
    }

    ulonglong2 bp = *(const ulonglong2*)&bin[tn0 + tx * 4];
#pragma unroll
    for (int i = 0; i < 8; i++) {
        ulonglong2 st;
        st.x = addf2(acc01[i], bp.x);
        st.y = addf2(acc23[i], bp.y);
        *(ulonglong2*)&out[(size_t)(tm0 + ty * 8 + i) * DOUT + tn0 + tx * 4] = st;
    }
}

// ---------------------------------------------------------------------------
// Phase 2: 2 independent groups x 64 CTAs.
// CTA (g = bid>>6, colg = bid&63) owns rows [32g,+32) x cols [16*colg,+16).
// ---------------------------------------------------------------------------
#define NB2 128
#define NW2 16                        // warps per CTA (k-slices)
#define KSL 64                        // k per warp
#define PFD 8                         // prefetch ring depth (float4 x 8)
#define SWBYTES (DOUT * 16 * 4)       // 64 KB: sW[k][16 cols]
#define SMEM2 (SWBYTES + NW2 * 32 * 9 * 8)   // 64 KB sW + 36 KB sP

// Transposed hidden state, double-buffered by t parity: g_hT[buf][j*64 + r].
__device__ float g_hT[2][DOUT * B_];

// Per-CTA flags (128B apart); per-group release words (128B apart).
__device__ volatile unsigned g_flag[NB2 * 32];
__device__ volatile unsigned g_gen2[2 * 32];

// Per-group two-hop barrier (R5-proven shape, 64-CTA domain). Equality
// compares + strictly increasing targets => replay-safe.
__device__ __forceinline__ void gsync(int bid, int g, int colg, unsigned target)
{
    __syncthreads();
    if (threadIdx.x == 0) {
        __threadfence();
        g_flag[bid << 5] = target;
    }
    if (colg == 0) {                  // group leader: poll 64 flags, 2/lane
        if (threadIdx.x < 32) {
            const int b0 = (g << 6) + (int)threadIdx.x;
            while (g_flag[b0 << 5] != target ||
                   g_flag[(b0 + 32) << 5] != target) { }
            __syncwarp();
            if (threadIdx.x == 0) {
                __threadfence();
                g_gen2[g << 5] = target;
            }
        }
    } else if (threadIdx.x == 0) {
        while (g_gen2[g << 5] != target) { }
        __threadfence();
    }
    __syncthreads();
}

__global__ void __launch_bounds__(512, 1) phase2_rnn(
    const float* __restrict__ Wh, const float* __restrict__ periods,
    const float* __restrict__ shifts, float* __restrict__ out)
{
    extern __shared__ char smem_raw[];
    float* sW  = (float*)smem_raw;                // [k][16 cols], 64 KB
    ull*   sPu = (ull*)(smem_raw + SWBYTES);      // [(w*32+l)*9+i], 36 KB
    float* sPf = (float*)sPu;

    const int tid  = threadIdx.x;
    const int bid  = blockIdx.x;
    const int g    = bid >> 6;            // row-group (0..1)
    const int colg = bid & 63;            // col-group (0..63)
    const int j0   = colg * 16;           // first of 16 cols
    const int r0   = g * 32;              // first of 32 rows
    const int w    = tid >> 5;            // warp = k-slice (0..15)
    const int l    = tid & 31;
    const int rb   = l & 7;               // row block: rows r0+4rb..+3
    const int cb   = l >> 3;              // col block: cols j0+4cb..+3

    // One-time: stage this CTA's 16 W_h columns, k-major (64 B per k).
    for (int i = tid; i < DOUT * 16; i += 512) {
        int k = i >> 4, c = i & 15;
        sW[i] = Wh[(size_t)k * DOUT + j0 + c];
    }
    const float per = periods[colg >> 3]; // 16 cols lie inside one module
    const float shf = shifts[colg >> 3];

    // Tail/epilogue mapping: thread -> one scalar (row r, col c).
    const int r  = tid >> 4;              // 0..31
    const int c  = tid & 15;              // 0..15
    const int gr = r0 + r;                // global batch row
    const int gj = j0 + c;                // global col
    // Source coords in sP: producing lane = cb*8+rb, ull index, half.
    const int s_lane = ((c >> 2) << 3) + (r >> 2);
    const int s_ull  = ((r & 3) << 1) + ((c & 3) >> 1);
    const int s_half = c & 1;
    __syncthreads();

    // ---- t = 0: h_prev = 0 -> y = (1-g) * tanh(u). ----
    {
        float g0 = (sinf(shf) + 1.f) * 0.5f;
        size_t ob = (size_t)gr * BSTR + gj;
        float y = (1.f - g0) * tanhf(out[ob]);
        out[ob] = y;
        g_hT[0][gj * B_ + gr] = y;
    }
    gsync(bid, g, colg, 1u);

    const int kbase = w << 6;             // this warp's K-slice base

    for (int t = 1; t < T_; t++) {
        const float* __restrict__ hsrc = g_hT[(t - 1) & 1];
        float*       __restrict__ hdst = g_hT[t & 1];

        // Hoisted epilogue loads (latency hidden under the mainloop).
        size_t ob = (size_t)gr * BSTR + (size_t)t * DOUT + gj;
        float uv = __ldcg(&out[ob]);
        float hp = __ldcg(&hsrc[gj * B_ + gr]);

        // Mainloop: 64 k per warp. Lane: 4 rows (LDG.128, own group rows
        // only) x 4 cols (16B LDS, uniform per 8-lane group).
        const float* hs = hsrc + (kbase << 6) + r0 + (rb << 2);
        ull a[8];
#pragma unroll
        for (int i = 0; i < 8; i++) a[i] = 0ull;
        float4 hbuf[PFD];
#pragma unroll
        for (int j = 0; j < PFD; j++)
            hbuf[j] = __ldcg((const float4*)(hs + (j << 6)));

#pragma unroll
        for (int kk = 0; kk < KSL; kk += PFD) {
#pragma unroll
            for (int j = 0; j < PFD; j++) {
                float4 h4 = hbuf[j];
                const int knext = kk + PFD + j;
                if (knext < KSL)
                    hbuf[j] = __ldcg((const float4*)(hs + (knext << 6)));
                // 16B of W: cols j0+4cb..+3 at this k.
                ulonglong2 wv = *(const ulonglong2*)
                    &sW[((kbase + kk + j) << 4) + (cb << 2)];
                ull h0 = dupf(h4.x), h1 = dupf(h4.y);
                ull h2 = dupf(h4.z), h3 = dupf(h4.w);
                ffma2(a[0], h0, wv.x); ffma2(a[1], h0, wv.y);  // row 4rb+0
                ffma2(a[2], h1, wv.x); ffma2(a[3], h1, wv.y);  // row 4rb+1
                ffma2(a[4], h2, wv.x); ffma2(a[5], h2, wv.y);  // row 4rb+2
                ffma2(a[6], h3, wv.x); ffma2(a[7], h3, wv.y);  // row 4rb+3
            }
        }

        // Partials: 8 ull per lane, 9-ull pitch (pad) to cap conflicts.
        {
            ull* p = sPu + ((w << 5) + l) * 9;
            p[0] = a[0]; p[1] = a[1]; p[2] = a[2]; p[3] = a[3];
            p[4] = a[4]; p[5] = a[5]; p[6] = a[6]; p[7] = a[7];
        }
        __syncthreads();

        // Full-width tail: thread (r, c) tree-sums its 16 partials.
        float p[NW2];
#pragma unroll
        for (int w2 = 0; w2 < NW2; w2++)
            p[w2] = sPf[((((w2 << 5) + s_lane) * 9 + s_ull) << 1) + s_half];
        float s01 = p[0] + p[1],   s23 = p[2] + p[3];
        float s45 = p[4] + p[5],   s67 = p[6] + p[7];
        float s89 = p[8] + p[9],   sab = p[10] + p[11];
        float scd = p[12] + p[13], sef = p[14] + p[15];
        float hv = ((s01 + s23) + (s45 + s67)) + ((s89 + sab) + (scd + sef));

        float gg = (sinf((float)t * per + shf) + 1.f) * 0.5f;
        float y = (1.f - gg) * tanhf(uv + hv) + gg * hp;

        // Critical path: ONLY the h the other CTAs need, then arrive.
        hdst[gj * B_ + gr] = y;
        gsync(bid, g, colg, (unsigned)(t + 1));   // fence+flag inside

        // Off critical path (overlaps next step's slack): ys + h_final.
        out[ob] = y;
        if (t == T_ - 1)
            out[YS_ELEMS + (size_t)gr * DOUT + gj] = y;
    }
}

// ---------------------------------------------------------------------------
extern "C" void kernel_launch(void* const* d_in, const int* in_sizes, int n_in,
                              void* d_out, int out_size)
{
    (void)in_sizes; (void)n_in; (void)out_size;
    const float* x       = (const float*)d_in[0];
    const float* W_in    = (const float*)d_in[1];
    const float* b_in    = (const float*)d_in[2];
    const float* W_h     = (const float*)d_in[3];
    const float* periods = (const float*)d_in[4];
    const float* shifts  = (const float*)d_in[5];
    float* out = (float*)d_out;

    // Opt-in smem above 48 KB (function-state call, capture-legal).
    cudaFuncSetAttribute(phase2_rnn,
                         cudaFuncAttributeMaxDynamicSharedMemorySize, SMEM2);

    dim3 g1(DOUT / 64, (B_ * T_) / 128);       // (16, 256)
    phase1_gemm<<<g1, 256>>>(x, W_in, b_in, out);
    phase2_rnn<<<NB2, 512, SMEM2>>>(W_h, periods, shifts, out);
}

// round 17
// speedup vs baseline: 1.1852x; 1.1852x over previous
#include <cuda_runtime.h>
#include <cuda_bf16.h>
#include <math.h>

// Problem shape (fixed by the dataset):
//   B=64, T=512, D_in=256, D_out=1024, M=8 (module_size=128)
// Phase 1: u = x@W_in + b_in into the ys region of d_out (f32x2 GEMM).
// Phase 2: persistent 128 CTAs x 512 threads, R14 mainloop (CTA = 8 cols x
//   64 rows; warp = 64-k slice; lane = 4 rows (LDG.128) x 4 cols (16B LDS));
//   BARRIER ELIMINATED -> data-flow sync: producer CTA c flags its 8-col h
//   chunk; consumer warp w polls only its 8 producers [8w,8w+8) at the top
//   of its k-slice. Skew is bounded at <=1 step by the all-columns
//   dependency (CTA p cannot finish mainloop t+1 -- and thus cannot
//   overwrite buffer (t-1)&1 or advance its flag -- until every CTA flagged
//   step t). Parity-slot flags + exact-equality handle skew-1 and graph
//   replay staleness (flag values are >=1; zero-init / stale never match).

#define B_      64
#define T_      512
#define DIN     256
#define DOUT    1024
#define BSTR    ((size_t)T_ * DOUT)
#define YS_ELEMS ((size_t)B_ * T_ * DOUT)

typedef unsigned long long ull;

// ---------------------------------------------------------------------------
// Packed-fp32 helpers (Blackwell f32x2)
// ---------------------------------------------------------------------------
__device__ __forceinline__ ull dupf(float x) {
    ull r;
    asm("mov.b64 %0, {%1, %1};" : "=l"(r) : "f"(x));
    return r;
}
__device__ __forceinline__ void ffma2(ull& d, ull a, ull b) {
    asm("fma.rn.f32x2 %0, %1, %2, %0;" : "+l"(d) : "l"(a), "l"(b));
}
__device__ __forceinline__ ull addf2(ull a, ull b) {
    ull r;
    asm("add.rn.f32x2 %0, %1, %2;" : "=l"(r) : "l"(a), "l"(b));
    return r;
}

// ---------------------------------------------------------------------------
// Phase 1: u = X @ W_in + b_in     (M=32768, N=1024, K=256)  [unchanged]
// ---------------------------------------------------------------------------
__global__ void __launch_bounds__(256) phase1_gemm(
    const float* __restrict__ X, const float* __restrict__ Win,
    const float* __restrict__ bin, float* __restrict__ out)
{
    __shared__ float As[16 * 132];
    __shared__ float Bs[16 * 68];

    const int tid = threadIdx.x;
    const int tn0 = blockIdx.x * 64;
    const int tm0 = blockIdx.y * 128;
    const int ty  = tid >> 4;
    const int tx  = tid & 15;

    ull acc01[8], acc23[8];
#pragma unroll
    for (int i = 0; i < 8; i++) { acc01[i] = 0ull; acc23[i] = 0ull; }

    const int arow  = tid >> 1;
    const int akoff = (tid & 1) * 8;
    const int bk    = tid >> 4;
    const int bn    = (tid & 15) * 4;

    for (int kc = 0; kc < DIN; kc += 16) {
        const float* ap = &X[(size_t)(tm0 + arow) * DIN + kc + akoff];
        float4 a0 = *(const float4*)(ap);
        float4 a1 = *(const float4*)(ap + 4);
        float4 b0 = *(const float4*)&Win[(size_t)(kc + bk) * DOUT + tn0 + bn];

        __syncthreads();
        As[(akoff + 0) * 132 + arow] = a0.x;
        As[(akoff + 1) * 132 + arow] = a0.y;
        As[(akoff + 2) * 132 + arow] = a0.z;
        As[(akoff + 3) * 132 + arow] = a0.w;
        As[(akoff + 4) * 132 + arow] = a1.x;
        As[(akoff + 5) * 132 + arow] = a1.y;
        As[(akoff + 6) * 132 + arow] = a1.z;
        As[(akoff + 7) * 132 + arow] = a1.w;
        *(float4*)&Bs[bk * 68 + bn] = b0;
        __syncthreads();

#pragma unroll
        for (int kk = 0; kk < 16; kk++) {
            float4 af0 = *(const float4*)&As[kk * 132 + ty * 8];
            float4 af1 = *(const float4*)&As[kk * 132 + ty * 8 + 4];
            ulonglong2 bb = *(const ulonglong2*)&Bs[kk * 68 + tx * 4];
            float a[8] = {af0.x, af0.y, af0.z, af0.w, af1.x, af1.y, af1.z, af1.w};
#pragma unroll
            for (int i = 0; i < 8; i++) {
                ull ad = dupf(a[i]);
                ffma2(acc01[i], ad, bb.x);
                ffma2(acc23[i], ad, bb.y);
            }
        }
    }

    ulonglong2 bp = *(const ulonglong2*)&bin[tn0 + tx * 4];
#pragma unroll
    for (int i = 0; i < 8; i++) {
        ulonglong2 st;
        st.x = addf2(acc01[i], bp.x);
        st.y = addf2(acc23[i], bp.y);
        *(ulonglong2*)&out[(size_t)(tm0 + ty * 8 + i) * DOUT + tn0 + tx * 4] = st;
    }
}

// ---------------------------------------------------------------------------
// Phase 2: persistent recurrence. 128 CTAs x 512 threads, 8 cols per CTA.
// Data-flow sync (no grid barrier).
// ---------------------------------------------------------------------------
#define NB2 128
#define NW2 16                        // warps per CTA (k-slices)
#define KSL 64                        // k per warp
#define PFD 8                         // prefetch ring depth (float4 x 8)
#define SMEM2 (DOUT * 4 * 8 + NW2 * 32 * 9 * 8)   // 32 KB sW + 36 KB sP

// Transposed hidden state, double-buffered by t parity: g_hT[buf][j*64 + r].
__device__ float g_hT[2][DOUT * B_];

// Parity-slot producer flags, 128B apart. pf[s][c] = t+1 after producer c
// finishes step t (t & 1 == s). Values are >= 1, so zero-init and stale
// replay contents never match a fresh target.
__device__ volatile unsigned g_pf[2][NB2 * 32];

__global__ void __launch_bounds__(512, 1) phase2_rnn(
    const float* __restrict__ Wh, const float* __restrict__ periods,
    const float* __restrict__ shifts, float* __restrict__ out)
{
    extern __shared__ char smem_raw[];
    float2* sW  = (float2*)smem_raw;                 // [k][col-pair], 32 KB
    ull*    sPu = (ull*)(smem_raw + DOUT * 4 * 8);   // [(w*32+l)*9+i], 36 KB
    float*  sPf = (float*)sPu;

    const int tid = threadIdx.x;
    const int bid = blockIdx.x;
    const int j0  = bid * 8;
    const int w   = tid >> 5;             // warp = k-slice (0..15)
    const int l   = tid & 31;
    const int li  = l & 15;               // row block: rows 4*li..4*li+3
    const int hf  = l >> 4;               // col half: cols j0+4*hf..+3

    // One-time: this CTA's 8 W_h columns as col-pairs.
    for (int i = tid; i < DOUT * 4; i += 512) {
        int k = i >> 2, cp = i & 3;
        sW[i] = make_float2(Wh[(size_t)k * DOUT + j0 + 2 * cp],
                            Wh[(size_t)k * DOUT + j0 + 2 * cp + 1]);
    }
    const float per = periods[bid >> 4];
    const float shf = shifts[bid >> 4];

    // Tail/epilogue mapping: thread -> one scalar (row er, col ec).
    const int er = tid >> 3;              // 0..63 (batch row)
    const int ec = tid & 7;               // 0..7  (col within CTA)
    const int gj = j0 + ec;               // global col
    // Source coordinates in sP: producing lane, ull index, half.
    const int s_lane = ((ec >> 2) << 4) + (er >> 2);          // hf*16 + li
    const int s_ull  = ((er & 3) << 1) + ((ec & 3) >> 1);     // r*2 + cu
    const int s_half = ec & 1;
    __syncthreads();

    // ---- t = 0: h_prev = 0 -> y = (1-g) * tanh(u). ----
    {
        float g0 = (sinf(shf) + 1.f) * 0.5f;
        size_t ob = (size_t)er * BSTR + gj;
        float y = (1.f - g0) * tanhf(out[ob]);
        out[ob] = y;
        g_hT[0][gj * B_ + er] = y;
    }
    __syncthreads();                      // CTA's h_0 chunk fully written
    if (tid == 0) {
        __threadfence();
        g_pf[0][bid << 5] = 1u;           // flag: step 0 done
    }

    const int kbase = w << 6;             // this warp's K-slice base
    // This warp's 8 producer CTAs: [8w, 8w+8). Lane < 8 polls one each.
    const int myprod = (w << 3) + l;      // valid for l < 8

    for (int t = 1; t < T_; t++) {
        const float* __restrict__ hsrc = g_hT[(t - 1) & 1];
        float*       __restrict__ hdst = g_hT[t & 1];

        // Data-flow wait: h_{t-1} chunks from this warp's 8 producers.
        if (l < 8) {
            const volatile unsigned* f = &g_pf[(t - 1) & 1][myprod << 5];
            while (*f != (unsigned)t) { }
        }
        __syncwarp();
        __threadfence();                  // acquire: order h reads after flags

        // Hoisted epilogue loads (own CTA's data: ready by CTA-local order).
        size_t ob = (size_t)er * BSTR + (size_t)t * DOUT + gj;
        float uv = __ldcg(&out[ob]);
        float hp = __ldcg(&hsrc[gj * B_ + er]);

        // Mainloop: 64 k per warp. Lane: 4 rows (LDG.128) x 4 cols (16B LDS,
        // uniform per half-warp). 8 FFMA2 per k vs 2 mem instrs.
        const float* hs = hsrc + (kbase << 6) + (li << 2);
        ull a[8];
#pragma unroll
        for (int i = 0; i < 8; i++) a[i] = 0ull;
        float4 hbuf[PFD];
#pragma unroll
        for (int j = 0; j < PFD; j++)
            hbuf[j] = __ldcg((const float4*)(hs + (j << 6)));

#pragma unroll
        for (int kk = 0; kk < KSL; kk += PFD) {
#pragma unroll
            for (int j = 0; j < PFD; j++) {
                float4 h4 = hbuf[j];
                const int knext = kk + PFD + j;
                if (knext < KSL)
                    hbuf[j] = __ldcg((const float4*)(hs + (knext << 6)));
                // 16B of W: cols j0+4hf .. j0+4hf+3 at k.
                ulonglong2 wv = *(const ulonglong2*)
                    &sW[((kbase + kk + j) << 2) + (hf << 1)];
                ull h0 = dupf(h4.x), h1 = dupf(h4.y);
                ull h2 = dupf(h4.z), h3 = dupf(h4.w);
                ffma2(a[0], h0, wv.x); ffma2(a[1], h0, wv.y);   // row 4li+0
                ffma2(a[2], h1, wv.x); ffma2(a[3], h1, wv.y);   // row 4li+1
                ffma2(a[4], h2, wv.x); ffma2(a[5], h2, wv.y);   // row 4li+2
                ffma2(a[6], h3, wv.x); ffma2(a[7], h3, wv.y);   // row 4li+3
            }
        }

        // Partials: 8 ull per lane, 9-ull pitch (pad) to cap conflicts.
        {
            ull* p = sPu + ((w << 5) + l) * 9;
            p[0] = a[0]; p[1] = a[1]; p[2] = a[2]; p[3] = a[3];
            p[4] = a[4]; p[5] = a[5]; p[6] = a[6]; p[7] = a[7];
        }
        __syncthreads();

        // Full-width tail: thread (er, ec) tree-sums its 16 partials.
        float p[NW2];
#pragma unroll
        for (int w2 = 0; w2 < NW2; w2++)
            p[w2] = sPf[((((w2 << 5) + s_lane) * 9 + s_ull) << 1) + s_half];
        float s01 = p[0] + p[1],   s23 = p[2] + p[3];
        float s45 = p[4] + p[5],   s67 = p[6] + p[7];
        float s89 = p[8] + p[9],   sab = p[10] + p[11];
        float scd = p[12] + p[13], sef = p[14] + p[15];
        float hv = ((s01 + s23) + (s45 + s67)) + ((s89 + sab) + (scd + sef));

        float gg = (sinf((float)t * per + shf) + 1.f) * 0.5f;
        float y = (1.f - gg) * tanhf(uv + hv) + gg * hp;
        out[ob] = y;
        hdst[gj * B_ + er] = y;
        if (t == T_ - 1)                  // h_final = ys[:, T-1, :]
            out[YS_ELEMS + (size_t)er * DOUT + gj] = y;

        // CTA-wide completion (also fences sPu reuse), then publish flag.
        __syncthreads();
        if (tid == 0) {
            __threadfence();
            g_pf[t & 1][bid << 5] = (unsigned)(t + 1);
        }
    }
}

// ---------------------------------------------------------------------------
extern "C" void kernel_launch(void* const* d_in, const int* in_sizes, int n_in,
                              void* d_out, int out_size)
{
    (void)in_sizes; (void)n_in; (void)out_size;
    const float* x       = (const float*)d_in[0];
    const float* W_in    = (const float*)d_in[1];
    const float* b_in    = (const float*)d_in[2];
    const float* W_h     = (const float*)d_in[3];
    const float* periods = (const float*)d_in[4];
    const float* shifts  = (const float*)d_in[5];
    float* out = (float*)d_out;

    // Opt-in smem above 48 KB (function-state call, capture-legal).
    cudaFuncSetAttribute(phase2_rnn,
                         cudaFuncAttributeMaxDynamicSharedMemorySize, SMEM2);

    dim3 g1(DOUT / 64, (B_ * T_) / 128);       // (16, 256)
    phase1_gemm<<<g1, 256>>>(x, W_in, b_in, out);
    phase2_rnn<<<NB2, 512, SMEM2>>>(W_h, periods, shifts, out);
}